// round 1
// baseline (speedup 1.0000x reference)
#include <cuda_runtime.h>

// Inverse db4 wavelet reconstruction.
// in : [B=16, L=16000, 128]  (first 64 ch = approx, last 64 = detail)
// out: [B=16, 2L=32000, 64]
//
// Math (derived from zero-upsample + SAME corr, pad_left=3):
//   out[2k]   = f1*x[k-1] + f3*x[k] + f5*x[k+1] + f7*x[k+2]
//   out[2k+1] = f0*x[k-1] + f2*x[k] + f4*x[k+1] + f6*x[k+2]
// applied with rec_lo on approx and rec_hi on detail, summed. x out of [0,L) is zero.

#define BATCH 16
#define SEQ_L 16000
#define C_IN  128
#define C_OUT 64
#define KPT   8          // k positions per thread
#define TPB   256        // 16 c4-groups x 16 k-tiles per block

__device__ __forceinline__ float4 f4zero() { return make_float4(0.f, 0.f, 0.f, 0.f); }

__device__ __forceinline__ void f4fma(float s, const float4& a, float4& acc) {
    acc.x = fmaf(s, a.x, acc.x);
    acc.y = fmaf(s, a.y, acc.y);
    acc.z = fmaf(s, a.z, acc.z);
    acc.w = fmaf(s, a.w, acc.w);
}

__global__ __launch_bounds__(TPB)
void idwt_db4_kernel(const float* __restrict__ in,
                     const float* __restrict__ rec_lo,
                     const float* __restrict__ rec_hi,
                     float* __restrict__ out)
{
    const int tid = threadIdx.x;
    const int c4  = tid & 15;          // which group of 4 channels (0..15)
    const int lk  = tid >> 4;          // local k-tile within block (0..15)

    constexpr int KTILES_PER_BLOCK = TPB / 16;                 // 16
    constexpr int BLOCKS_PER_BATCH = SEQ_L / (KPT * KTILES_PER_BLOCK); // 16000/128 = 125

    const int b   = blockIdx.x / BLOCKS_PER_BATCH;
    const int blk = blockIdx.x % BLOCKS_PER_BATCH;
    const int k0  = (blk * KTILES_PER_BLOCK + lk) * KPT;

    // filter taps (uniform broadcast loads)
    const float l0 = __ldg(rec_lo + 0), l1 = __ldg(rec_lo + 1);
    const float l2 = __ldg(rec_lo + 2), l3 = __ldg(rec_lo + 3);
    const float l4 = __ldg(rec_lo + 4), l5 = __ldg(rec_lo + 5);
    const float l6 = __ldg(rec_lo + 6), l7 = __ldg(rec_lo + 7);
    const float h0 = __ldg(rec_hi + 0), h1 = __ldg(rec_hi + 1);
    const float h2 = __ldg(rec_hi + 2), h3 = __ldg(rec_hi + 3);
    const float h4 = __ldg(rec_hi + 4), h5 = __ldg(rec_hi + 5);
    const float h6 = __ldg(rec_hi + 6), h7 = __ldg(rec_hi + 7);

    const float* ap = in + (size_t)b * SEQ_L * C_IN + c4 * 4;        // approx base
    const float* dp = ap + C_OUT;                                    // detail base
    float* op = out + (size_t)b * (2 * SEQ_L) * C_OUT + c4 * 4;

    auto ld = [&](const float* base, int k) -> float4 {
        if ((unsigned)k < (unsigned)SEQ_L)
            return *reinterpret_cast<const float4*>(base + (size_t)k * C_IN);
        return f4zero();
    };

    // sliding window registers: x[k-1], x[k], x[k+1]; x[k+2] loaded per iter
    float4 am1 = ld(ap, k0 - 1), a0 = ld(ap, k0), a1 = ld(ap, k0 + 1);
    float4 dm1 = ld(dp, k0 - 1), d0 = ld(dp, k0), d1 = ld(dp, k0 + 1);

#pragma unroll
    for (int i = 0; i < KPT; ++i) {
        const int k = k0 + i;
        float4 a2 = ld(ap, k + 2);
        float4 d2 = ld(dp, k + 2);

        float4 ev = f4zero();   // out[2k]
        f4fma(l1, am1, ev); f4fma(l3, a0, ev); f4fma(l5, a1, ev); f4fma(l7, a2, ev);
        f4fma(h1, dm1, ev); f4fma(h3, d0, ev); f4fma(h5, d1, ev); f4fma(h7, d2, ev);

        float4 od = f4zero();   // out[2k+1]
        f4fma(l0, am1, od); f4fma(l2, a0, od); f4fma(l4, a1, od); f4fma(l6, a2, od);
        f4fma(h0, dm1, od); f4fma(h2, d0, od); f4fma(h4, d1, od); f4fma(h6, d2, od);

        *reinterpret_cast<float4*>(op + (size_t)(2 * k)     * C_OUT) = ev;
        *reinterpret_cast<float4*>(op + (size_t)(2 * k + 1) * C_OUT) = od;

        am1 = a0; a0 = a1; a1 = a2;
        dm1 = d0; d0 = d1; d1 = d2;
    }
}

extern "C" void kernel_launch(void* const* d_in, const int* in_sizes, int n_in,
                              void* d_out, int out_size)
{
    const float* in     = (const float*)d_in[0];
    const float* rec_lo = (const float*)d_in[1];
    const float* rec_hi = (const float*)d_in[2];
    float* out          = (float*)d_out;

    constexpr int KTILES_PER_BLOCK = TPB / 16;
    constexpr int BLOCKS_PER_BATCH = SEQ_L / (KPT * KTILES_PER_BLOCK); // 125
    const dim3 grid(BATCH * BLOCKS_PER_BATCH);                         // 2000 blocks

    idwt_db4_kernel<<<grid, TPB>>>(in, rec_lo, rec_hi, out);
}

// round 2
// speedup vs baseline: 1.0909x; 1.0909x over previous
#include <cuda_runtime.h>

// Inverse db4 wavelet reconstruction (polyphase form).
// in : [B=16, L=16000, 128]  (first 64 ch = approx, last 64 = detail)
// out: [B=16, 2L=32000, 64]
//
//   out[2k]   = l1*a[k-1]+l3*a[k]+l5*a[k+1]+l7*a[k+2] + h1*d[k-1]+h3*d[k]+h5*d[k+1]+h7*d[k+2]
//   out[2k+1] = l0*a[k-1]+l2*a[k]+l4*a[k+1]+l6*a[k+2] + h0*d[k-1]+h2*d[k]+h4*d[k+1]+h6*d[k+2]
// x out of [0,L) is zero.

#define BATCH 16
#define SEQ_L 16000
#define C_IN  128
#define C_OUT 64
#define KPT   8          // k positions per thread
#define NW    (KPT + 3)  // rows in the load window
#define TPB   128        // 16 c4-groups x 8 k-tiles per block

__device__ __forceinline__ float4 f4zero() { return make_float4(0.f, 0.f, 0.f, 0.f); }

__device__ __forceinline__ void f4fma(float s, const float4& a, float4& acc) {
    acc.x = fmaf(s, a.x, acc.x);
    acc.y = fmaf(s, a.y, acc.y);
    acc.z = fmaf(s, a.z, acc.z);
    acc.w = fmaf(s, a.w, acc.w);
}

__global__ __launch_bounds__(TPB)
void idwt_db4_kernel(const float* __restrict__ in,
                     const float* __restrict__ rec_lo,
                     const float* __restrict__ rec_hi,
                     float* __restrict__ out)
{
    const int tid = threadIdx.x;
    const int c4  = tid & 15;          // channel group of 4 (0..15)
    const int lk  = tid >> 4;          // local k-tile (0..7)

    constexpr int KTILES_PER_BLOCK = TPB / 16;                          // 8
    constexpr int BLOCKS_PER_BATCH = SEQ_L / (KPT * KTILES_PER_BLOCK);  // 250

    const int b   = blockIdx.x / BLOCKS_PER_BATCH;
    const int blk = blockIdx.x % BLOCKS_PER_BATCH;
    const int k0  = (blk * KTILES_PER_BLOCK + lk) * KPT;

    const float l0 = __ldg(rec_lo + 0), l1 = __ldg(rec_lo + 1);
    const float l2 = __ldg(rec_lo + 2), l3 = __ldg(rec_lo + 3);
    const float l4 = __ldg(rec_lo + 4), l5 = __ldg(rec_lo + 5);
    const float l6 = __ldg(rec_lo + 6), l7 = __ldg(rec_lo + 7);
    const float h0 = __ldg(rec_hi + 0), h1 = __ldg(rec_hi + 1);
    const float h2 = __ldg(rec_hi + 2), h3 = __ldg(rec_hi + 3);
    const float h4 = __ldg(rec_hi + 4), h5 = __ldg(rec_hi + 5);
    const float h6 = __ldg(rec_hi + 6), h7 = __ldg(rec_hi + 7);

    const float* ap = in + (size_t)b * SEQ_L * C_IN + c4 * 4;   // approx base
    float* op = out + (size_t)b * (2 * SEQ_L) * C_OUT + c4 * 4;

    float4 a[NW], d[NW];

    if (k0 >= 1 && k0 + KPT + 2 <= SEQ_L) {
        // Interior: unpredicated, front-batched loads (MLP ~22 per thread).
        const float* p = ap + (size_t)(k0 - 1) * C_IN;
#pragma unroll
        for (int i = 0; i < NW; ++i) {
            a[i] = *reinterpret_cast<const float4*>(p + (size_t)i * C_IN);
            d[i] = *reinterpret_cast<const float4*>(p + (size_t)i * C_IN + C_OUT);
        }
    } else {
        // Batch edge: predicated loads with zero fill.
#pragma unroll
        for (int i = 0; i < NW; ++i) {
            const int k = k0 - 1 + i;
            if ((unsigned)k < (unsigned)SEQ_L) {
                const float* p = ap + (size_t)k * C_IN;
                a[i] = *reinterpret_cast<const float4*>(p);
                d[i] = *reinterpret_cast<const float4*>(p + C_OUT);
            } else {
                a[i] = f4zero();
                d[i] = f4zero();
            }
        }
    }

#pragma unroll
    for (int i = 0; i < KPT; ++i) {
        const int k = k0 + i;

        float4 ev = f4zero();   // out[2k]
        f4fma(l1, a[i], ev); f4fma(l3, a[i + 1], ev); f4fma(l5, a[i + 2], ev); f4fma(l7, a[i + 3], ev);
        f4fma(h1, d[i], ev); f4fma(h3, d[i + 1], ev); f4fma(h5, d[i + 2], ev); f4fma(h7, d[i + 3], ev);

        float4 od = f4zero();   // out[2k+1]
        f4fma(l0, a[i], od); f4fma(l2, a[i + 1], od); f4fma(l4, a[i + 2], od); f4fma(l6, a[i + 3], od);
        f4fma(h0, d[i], od); f4fma(h2, d[i + 1], od); f4fma(h4, d[i + 2], od); f4fma(h6, d[i + 3], od);

        __stcs(reinterpret_cast<float4*>(op + (size_t)(2 * k) * C_OUT), ev);
        __stcs(reinterpret_cast<float4*>(op + (size_t)(2 * k + 1) * C_OUT), od);
    }
}

extern "C" void kernel_launch(void* const* d_in, const int* in_sizes, int n_in,
                              void* d_out, int out_size)
{
    const float* in     = (const float*)d_in[0];
    const float* rec_lo = (const float*)d_in[1];
    const float* rec_hi = (const float*)d_in[2];
    float* out          = (float*)d_out;

    constexpr int KTILES_PER_BLOCK = TPB / 16;                          // 8
    constexpr int BLOCKS_PER_BATCH = SEQ_L / (KPT * KTILES_PER_BLOCK);  // 250
    const dim3 grid(BATCH * BLOCKS_PER_BATCH);                          // 4000 blocks

    idwt_db4_kernel<<<grid, TPB>>>(in, rec_lo, rec_hi, out);
}